// round 1
// baseline (speedup 1.0000x reference)
#include <cuda_runtime.h>
#include <math.h>

// Problem constants (fixed by the reference)
#define B_    4
#define S_    2048
#define H_    4096
#define E_    8
#define K_    2
#define A_    64
#define NTOK  (B_ * S_)          // 8192
#define SCALE 2.0f

// Fused kernel: one block per token.
//  - 8 warps compute the 8 router logits (fp32, exact)
//  - thread 0 does top-2 + softmax
//  - down-proj: 256 threads cover 2 slots x 64 adapter dims x 2 H-halves
//  - exact gelu (erff)
//  - up-proj fused with "o +" epilogue, float4 streams on Wu
__global__ __launch_bounds__(256)
void moe_fused_kernel(const float* __restrict__ x_all,
                      const float* __restrict__ o_all,
                      const float* __restrict__ r_all,
                      const float* __restrict__ Wr,
                      const float* __restrict__ Wd,
                      const float* __restrict__ Wu,
                      float* __restrict__ out,
                      float* __restrict__ logits_out) {
    const int n = blockIdx.x;
    const float* x = x_all + (size_t)n * H_;
    const float* r = r_all + (size_t)n * H_;
    const float* o = o_all + (size_t)n * H_;
    float* outr = out + (size_t)n * H_;

    __shared__ float xs[H_];          // 16 KB staged input row
    __shared__ float red[256];        // reduction scratch
    __shared__ float hs[K_][A_];      // gelu(down) activations
    __shared__ float logit_s[E_];
    __shared__ int   eidx_s[K_];
    __shared__ float ew_s[K_];

    const int tid  = threadIdx.x;
    const int lane = tid & 31;
    const int wid  = tid >> 5;

    // ---- stage x into smem (coalesced float4) ----
    {
        const float4* xv = (const float4*)x;
        float4* xsv = (float4*)xs;
        #pragma unroll 4
        for (int i = tid; i < H_ / 4; i += 256) xsv[i] = xv[i];
    }

    // ---- router: warp w computes logit for expert w ----
    {
        const float4* rv = (const float4*)r;
        const float4* wv = (const float4*)(Wr + (size_t)wid * H_);
        float acc = 0.f;
        #pragma unroll 4
        for (int i = lane; i < H_ / 4; i += 32) {
            float4 a = rv[i];
            float4 b = wv[i];
            acc += a.x * b.x + a.y * b.y + a.z * b.z + a.w * b.w;
        }
        #pragma unroll
        for (int s = 16; s; s >>= 1) acc += __shfl_xor_sync(0xffffffffu, acc, s);
        if (lane == 0) logit_s[wid] = acc;
    }
    __syncthreads();

    // write router logits (second output, concatenated after `out`)
    if (tid < E_) logits_out[(size_t)n * E_ + tid] = logit_s[tid];

    // ---- top-2 + softmax (matches jax.lax.top_k tie-breaking: lowest index wins) ----
    if (tid == 0) {
        float v1 = -INFINITY; int i1 = 0;
        #pragma unroll
        for (int e = 0; e < E_; e++) {
            float v = logit_s[e];
            if (v > v1) { v1 = v; i1 = e; }
        }
        float v2 = -INFINITY; int i2 = 0;
        #pragma unroll
        for (int e = 0; e < E_; e++) {
            if (e == i1) continue;
            float v = logit_s[e];
            if (v > v2) { v2 = v; i2 = e; }
        }
        // softmax over {v1, v2}; v1 >= v2
        float e2 = expf(v2 - v1);
        float inv = 1.0f / (1.0f + e2);
        eidx_s[0] = i1; eidx_s[1] = i2;
        ew_s[0] = inv;  ew_s[1] = e2 * inv;
    }
    __syncthreads();

    // ---- down projection: h[slot][a] = gelu( dot(x, Wd[e_slot][a]) ) ----
    // 256 threads = 2 slots * 64 a * 2 halves-of-H
    {
        const int unit = tid >> 1;       // 0..127
        const int half = tid & 1;        // which half of H
        const int slot = unit >> 6;      // 0..1
        const int a    = unit & 63;      // 0..63
        const int e    = eidx_s[slot];

        const float4* wd = (const float4*)(Wd + ((size_t)e * A_ + a) * H_ + half * (H_ / 2));
        const float4* xv = (const float4*)(xs + half * (H_ / 2));
        float acc = 0.f;
        #pragma unroll 8
        for (int i = 0; i < H_ / 8; i++) {     // 512 float4 iters over 2048 elems
            float4 w = wd[i];
            float4 xq = xv[i];
            acc += xq.x * w.x + xq.y * w.y + xq.z * w.z + xq.w * w.w;
        }
        red[tid] = acc;
    }
    __syncthreads();
    if (tid < 128) {
        float v = red[2 * tid] + red[2 * tid + 1];
        // exact gelu: 0.5*v*(1+erf(v/sqrt(2)))
        float g = 0.5f * v * (1.0f + erff(v * 0.70710678118654752440f));
        hs[tid >> 6][tid & 63] = g;
    }
    __syncthreads();

    // ---- up projection + epilogue:
    // out[h] = o[h] + SCALE * (w1 * dot(h1, Wu[e1][h]) + w2 * dot(h2, Wu[e2][h]))
    {
        const int e1 = eidx_s[0], e2 = eidx_s[1];
        const float w1 = ew_s[0], w2 = ew_s[1];
        const float4* h1v = (const float4*)hs[0];
        const float4* h2v = (const float4*)hs[1];

        #pragma unroll 2
        for (int h = tid; h < H_; h += 256) {
            const float4* wu1 = (const float4*)(Wu + ((size_t)e1 * H_ + h) * A_);
            const float4* wu2 = (const float4*)(Wu + ((size_t)e2 * H_ + h) * A_);
            float y1 = 0.f, y2 = 0.f;
            #pragma unroll
            for (int i = 0; i < A_ / 4; i++) {   // 16 iters
                float4 hv = h1v[i];
                float4 wv = wu1[i];
                y1 += hv.x * wv.x + hv.y * wv.y + hv.z * wv.z + hv.w * wv.w;
                float4 hv2 = h2v[i];
                float4 wv2 = wu2[i];
                y2 += hv2.x * wv2.x + hv2.y * wv2.y + hv2.z * wv2.z + hv2.w * wv2.w;
            }
            outr[h] = o[h] + SCALE * (w1 * y1 + w2 * y2);
        }
    }
}

extern "C" void kernel_launch(void* const* d_in, const int* in_sizes, int n_in,
                              void* d_out, int out_size) {
    // metadata order: input_hidden_states, output_hidden_states, router_hidden_states, Wr, Wd, Wu
    const float* x  = (const float*)d_in[0];
    const float* o  = (const float*)d_in[1];
    const float* r  = (const float*)d_in[2];
    const float* Wr = (const float*)d_in[3];
    const float* Wd = (const float*)d_in[4];
    const float* Wu = (const float*)d_in[5];

    float* out = (float*)d_out;                       // [N, H] first
    float* logits = out + (size_t)NTOK * H_;          // [N, E] after

    moe_fused_kernel<<<NTOK, 256>>>(x, o, r, Wr, Wd, Wu, out, logits);
}

// round 2
// speedup vs baseline: 11.9284x; 11.9284x over previous
#include <cuda_runtime.h>
#include <math.h>
#include <stdint.h>

// ---------------- problem constants ----------------
#define B_    4
#define S_    2048
#define H_    4096
#define E_    8
#define A_    64
#define NTOK  (B_ * S_)       // 8192
#define EA    (E_ * A_)       // 512
#define SCALE 2.0f

// ---------------- scratch (static device memory; no allocation) ----------------
__device__ float g_coef[NTOK * E_];            // SCALE * combine weight (0 if unselected)
__device__ float g_G[(size_t)NTOK * EA];       // coef * gelu(X @ Wd^T)

// ---------------- helpers ----------------
__device__ __forceinline__ float f2tf32f(float f) {
    uint32_t u;
    asm("cvt.rna.tf32.f32 %0, %1;" : "=r"(u) : "f"(f));
    return __uint_as_float(u);
}

__device__ __forceinline__ void mma_tf32(float* c, const uint32_t* a, const uint32_t* b) {
    asm volatile(
        "mma.sync.aligned.m16n8k8.row.col.f32.tf32.tf32.f32 "
        "{%0,%1,%2,%3}, {%4,%5,%6,%7}, {%8,%9}, {%0,%1,%2,%3};"
        : "+f"(c[0]), "+f"(c[1]), "+f"(c[2]), "+f"(c[3])
        : "r"(a[0]), "r"(a[1]), "r"(a[2]), "r"(a[3]),
          "r"(b[0]), "r"(b[1]));
}

__device__ __forceinline__ float gelu_exact(float v) {
    return 0.5f * v * (1.0f + erff(v * 0.70710678118654752440f));
}

// ================= router kernel =================
// 256 threads = 8 warps, 2 tokens per warp -> 16 tokens per block, grid = 512.
// Wr chunk staged in smem; logits exact fp32; top-2 matches jax.lax.top_k
// tie-breaking (lowest index wins on ties via strict '>').
#define RT_CHUNK 1024
#define RT_TPW   2
#define RT_TPB   16

__global__ __launch_bounds__(256)
void router_kernel(const float* __restrict__ r_all,
                   const float* __restrict__ Wr,
                   float* __restrict__ logits_out) {
    __shared__ float wr_s[E_][RT_CHUNK];       // 32 KB

    const int tid  = threadIdx.x;
    const int lane = tid & 31;
    const int wid  = tid >> 5;
    const int tok0 = blockIdx.x * RT_TPB + wid * RT_TPW;

    float acc[RT_TPW][E_];
    #pragma unroll
    for (int t = 0; t < RT_TPW; t++)
        #pragma unroll
        for (int e = 0; e < E_; e++) acc[t][e] = 0.f;

    for (int c = 0; c < H_ / RT_CHUNK; c++) {
        __syncthreads();
        // load Wr chunk: 8 x 1024 floats = 2048 float4, 256 threads -> 8 each
        #pragma unroll
        for (int i = tid; i < E_ * RT_CHUNK / 4; i += 256) {
            int e  = i >> 8;              // i / 256
            int k4 = i & 255;             // i % 256
            float4 v = *(const float4*)(Wr + (size_t)e * H_ + c * RT_CHUNK + k4 * 4);
            *(float4*)&wr_s[e][k4 * 4] = v;
        }
        __syncthreads();

        #pragma unroll
        for (int t = 0; t < RT_TPW; t++) {
            const float4* rv = (const float4*)(r_all + (size_t)(tok0 + t) * H_ + c * RT_CHUNK);
            for (int k4 = lane; k4 < RT_CHUNK / 4; k4 += 32) {
                float4 r4 = rv[k4];
                #pragma unroll
                for (int e = 0; e < E_; e++) {
                    float4 w4 = *(const float4*)&wr_s[e][k4 * 4];
                    acc[t][e] += r4.x * w4.x + r4.y * w4.y + r4.z * w4.z + r4.w * w4.w;
                }
            }
        }
    }

    // butterfly reduce each accumulator across the warp
    #pragma unroll
    for (int t = 0; t < RT_TPW; t++)
        #pragma unroll
        for (int e = 0; e < E_; e++)
            #pragma unroll
            for (int s = 16; s; s >>= 1)
                acc[t][e] += __shfl_xor_sync(0xffffffffu, acc[t][e], s);

    if (lane == 0) {
        #pragma unroll
        for (int t = 0; t < RT_TPW; t++) {
            const int n = tok0 + t;
            float v1 = -INFINITY; int i1 = 0;
            #pragma unroll
            for (int e = 0; e < E_; e++) {
                logits_out[(size_t)n * E_ + e] = acc[t][e];
                if (acc[t][e] > v1) { v1 = acc[t][e]; i1 = e; }
            }
            float v2 = -INFINITY; int i2 = 0;
            #pragma unroll
            for (int e = 0; e < E_; e++) {
                if (e == i1) continue;
                if (acc[t][e] > v2) { v2 = acc[t][e]; i2 = e; }
            }
            float e2  = expf(v2 - v1);
            float w1  = 1.0f / (1.0f + e2);
            float w2  = e2 * w1;
            #pragma unroll
            for (int e = 0; e < E_; e++) {
                float cv = (e == i1) ? SCALE * w1 : ((e == i2) ? SCALE * w2 : 0.0f);
                g_coef[(size_t)n * E_ + e] = cv;
            }
        }
    }
}

// ================= GEMM tiling shared constants =================
// CTA tile 128x128, K chunk 32, 256 threads = 8 warps as 4(M) x 2(N),
// warp tile 32x64 = 2 M-frags x 8 N-frags of m16n8k8.
#define BM 128
#define BN 128
#define BK 32

// ================= down kernel: G = coef * gelu(X @ Wd^T) =================
// X: [NTOK, H] row-major.  Wd flat: [EA, H] row-major (== B col-major K x N).
__global__ __launch_bounds__(256)
void down_kernel(const float* __restrict__ X,
                 const float* __restrict__ Wd) {
    __shared__ float As[BM][BK + 4];
    __shared__ float Bs[BN][BK + 4];
    __shared__ float coef_s[BM][E_];

    const int tid  = threadIdx.x;
    const int lane = tid & 31;
    const int wid  = tid >> 5;
    const int g    = lane >> 2;
    const int tg   = lane & 3;
    const int wm   = (wid >> 1) * 32;
    const int wn   = (wid & 1) * 64;
    const int m0   = blockIdx.x * BM;
    const int n0   = blockIdx.y * BN;

    for (int i = tid; i < BM * E_; i += 256)
        coef_s[i / E_][i % E_] = g_coef[(size_t)m0 * E_ + i];

    float c[2][8][4];
    #pragma unroll
    for (int mi = 0; mi < 2; mi++)
        #pragma unroll
        for (int ni = 0; ni < 8; ni++)
            #pragma unroll
            for (int k = 0; k < 4; k++) c[mi][ni][k] = 0.f;

    const int lr = tid >> 3;            // 0..31
    const int lc = (tid & 7) * 4;       // 0..28

    for (int kt = 0; kt < H_ / BK; kt++) {
        float4 av[4], bv[4];
        #pragma unroll
        for (int i = 0; i < 4; i++) {
            av[i] = *(const float4*)(X  + (size_t)(m0 + lr + 32 * i) * H_ + kt * BK + lc);
            bv[i] = *(const float4*)(Wd + (size_t)(n0 + lr + 32 * i) * H_ + kt * BK + lc);
        }
        __syncthreads();
        #pragma unroll
        for (int i = 0; i < 4; i++) {
            As[lr + 32 * i][lc + 0] = f2tf32f(av[i].x);
            As[lr + 32 * i][lc + 1] = f2tf32f(av[i].y);
            As[lr + 32 * i][lc + 2] = f2tf32f(av[i].z);
            As[lr + 32 * i][lc + 3] = f2tf32f(av[i].w);
            Bs[lr + 32 * i][lc + 0] = f2tf32f(bv[i].x);
            Bs[lr + 32 * i][lc + 1] = f2tf32f(bv[i].y);
            Bs[lr + 32 * i][lc + 2] = f2tf32f(bv[i].z);
            Bs[lr + 32 * i][lc + 3] = f2tf32f(bv[i].w);
        }
        __syncthreads();

        #pragma unroll
        for (int ks = 0; ks < BK / 8; ks++) {
            uint32_t a[2][4], b[8][2];
            #pragma unroll
            for (int mi = 0; mi < 2; mi++) {
                int r0 = wm + mi * 16 + g;
                a[mi][0] = __float_as_uint(As[r0    ][ks * 8 + tg    ]);
                a[mi][1] = __float_as_uint(As[r0 + 8][ks * 8 + tg    ]);
                a[mi][2] = __float_as_uint(As[r0    ][ks * 8 + tg + 4]);
                a[mi][3] = __float_as_uint(As[r0 + 8][ks * 8 + tg + 4]);
            }
            #pragma unroll
            for (int ni = 0; ni < 8; ni++) {
                int nr = wn + ni * 8 + g;
                b[ni][0] = __float_as_uint(Bs[nr][ks * 8 + tg    ]);
                b[ni][1] = __float_as_uint(Bs[nr][ks * 8 + tg + 4]);
            }
            #pragma unroll
            for (int mi = 0; mi < 2; mi++)
                #pragma unroll
                for (int ni = 0; ni < 8; ni++)
                    mma_tf32(c[mi][ni], a[mi], b[ni]);
        }
    }

    // epilogue: gelu + coef, write G
    #pragma unroll
    for (int mi = 0; mi < 2; mi++) {
        #pragma unroll
        for (int ni = 0; ni < 8; ni++) {
            int r0 = wm + mi * 16 + g;
            int c0 = wn + ni * 8 + 2 * tg;
            #pragma unroll
            for (int q = 0; q < 4; q++) {
                int rr = r0 + (q >> 1) * 8;
                int cc = c0 + (q & 1);
                int e  = (n0 + cc) >> 6;
                float v = gelu_exact(c[mi][ni][q]) * coef_s[rr][e];
                g_G[(size_t)(m0 + rr) * EA + (n0 + cc)] = v;
            }
        }
    }
}

// ================= up kernel: out = o + G @ Wu^T_flat =================
// G: [NTOK, EA] row-major.  B[k=ea, n=h] = Wu[e][h][a]  (e=k>>6, a=k&63).
__global__ __launch_bounds__(256)
void up_kernel(const float* __restrict__ Wu,
               const float* __restrict__ o_all,
               float* __restrict__ out) {
    __shared__ float As[BM][BK + 4];
    __shared__ float Bs[BN][BK + 4];

    const int tid  = threadIdx.x;
    const int lane = tid & 31;
    const int wid  = tid >> 5;
    const int g    = lane >> 2;
    const int tg   = lane & 3;
    const int wm   = (wid >> 1) * 32;
    const int wn   = (wid & 1) * 64;
    const int m0   = blockIdx.x * BM;   // token
    const int n0   = blockIdx.y * BN;   // h

    float c[2][8][4];
    #pragma unroll
    for (int mi = 0; mi < 2; mi++)
        #pragma unroll
        for (int ni = 0; ni < 8; ni++)
            #pragma unroll
            for (int k = 0; k < 4; k++) c[mi][ni][k] = 0.f;

    const int lr = tid >> 3;
    const int lc = (tid & 7) * 4;

    for (int kt = 0; kt < EA / BK; kt++) {      // 16 chunks; expert e = kt>>1
        const int e     = kt >> 1;
        const int abase = (kt & 1) * 32;
        float4 av[4], bv[4];
        #pragma unroll
        for (int i = 0; i < 4; i++) {
            av[i] = *(const float4*)(g_G + (size_t)(m0 + lr + 32 * i) * EA + kt * BK + lc);
            bv[i] = *(const float4*)(Wu + ((size_t)e * H_ + (n0 + lr + 32 * i)) * A_ + abase + lc);
        }
        __syncthreads();
        #pragma unroll
        for (int i = 0; i < 4; i++) {
            As[lr + 32 * i][lc + 0] = f2tf32f(av[i].x);
            As[lr + 32 * i][lc + 1] = f2tf32f(av[i].y);
            As[lr + 32 * i][lc + 2] = f2tf32f(av[i].z);
            As[lr + 32 * i][lc + 3] = f2tf32f(av[i].w);
            Bs[lr + 32 * i][lc + 0] = f2tf32f(bv[i].x);
            Bs[lr + 32 * i][lc + 1] = f2tf32f(bv[i].y);
            Bs[lr + 32 * i][lc + 2] = f2tf32f(bv[i].z);
            Bs[lr + 32 * i][lc + 3] = f2tf32f(bv[i].w);
        }
        __syncthreads();

        #pragma unroll
        for (int ks = 0; ks < BK / 8; ks++) {
            uint32_t a[2][4], b[8][2];
            #pragma unroll
            for (int mi = 0; mi < 2; mi++) {
                int r0 = wm + mi * 16 + g;
                a[mi][0] = __float_as_uint(As[r0    ][ks * 8 + tg    ]);
                a[mi][1] = __float_as_uint(As[r0 + 8][ks * 8 + tg    ]);
                a[mi][2] = __float_as_uint(As[r0    ][ks * 8 + tg + 4]);
                a[mi][3] = __float_as_uint(As[r0 + 8][ks * 8 + tg + 4]);
            }
            #pragma unroll
            for (int ni = 0; ni < 8; ni++) {
                int nr = wn + ni * 8 + g;
                b[ni][0] = __float_as_uint(Bs[nr][ks * 8 + tg    ]);
                b[ni][1] = __float_as_uint(Bs[nr][ks * 8 + tg + 4]);
            }
            #pragma unroll
            for (int mi = 0; mi < 2; mi++)
                #pragma unroll
                for (int ni = 0; ni < 8; ni++)
                    mma_tf32(c[mi][ni], a[mi], b[ni]);
        }
    }

    // epilogue: out = o + contribution
    #pragma unroll
    for (int mi = 0; mi < 2; mi++) {
        #pragma unroll
        for (int ni = 0; ni < 8; ni++) {
            int r0 = wm + mi * 16 + g;
            int c0 = wn + ni * 8 + 2 * tg;
            #pragma unroll
            for (int q = 0; q < 4; q++) {
                int rr = r0 + (q >> 1) * 8;
                int cc = c0 + (q & 1);
                size_t idx = (size_t)(m0 + rr) * H_ + (n0 + cc);
                out[idx] = o_all[idx] + c[mi][ni][q];
            }
        }
    }
}

// ================= launch =================
extern "C" void kernel_launch(void* const* d_in, const int* in_sizes, int n_in,
                              void* d_out, int out_size) {
    const float* x  = (const float*)d_in[0];
    const float* o  = (const float*)d_in[1];
    const float* r  = (const float*)d_in[2];
    const float* Wr = (const float*)d_in[3];
    const float* Wd = (const float*)d_in[4];
    const float* Wu = (const float*)d_in[5];

    float* out    = (float*)d_out;                 // [NTOK, H]
    float* logits = out + (size_t)NTOK * H_;       // [NTOK, E]

    router_kernel<<<NTOK / RT_TPB, 256>>>(r, Wr, logits);
    down_kernel<<<dim3(NTOK / BM, EA / BN), 256>>>(x, Wd);
    up_kernel<<<dim3(NTOK / BM, H_ / BN), 256>>>(Wu, o, out);
}

// round 4
// speedup vs baseline: 20.3043x; 1.7022x over previous
#include <cuda_runtime.h>
#include <cuda_bf16.h>
#include <math.h>
#include <stdint.h>

// ---------------- problem constants ----------------
#define B_    4
#define S_    2048
#define H_    4096
#define E_    8
#define A_    64
#define NTOK  (B_ * S_)       // 8192
#define EA    (E_ * A_)       // 512
#define SCALE 2.0f

// ---------------- scratch (static device memory; no allocation) ----------------
__device__ float g_coef[NTOK * E_];                    // SCALE * combine weight (0 if unselected)
__device__ __nv_bfloat16 g_G[(size_t)NTOK * EA];       // coef * gelu(X @ Wd^T), bf16

// ---------------- helpers ----------------
__device__ __forceinline__ void mma_bf16(float* c, const uint32_t* a, const uint32_t* b) {
    asm volatile(
        "mma.sync.aligned.m16n8k16.row.col.f32.bf16.bf16.f32 "
        "{%0,%1,%2,%3}, {%4,%5,%6,%7}, {%8,%9}, {%0,%1,%2,%3};"
        : "+f"(c[0]), "+f"(c[1]), "+f"(c[2]), "+f"(c[3])
        : "r"(a[0]), "r"(a[1]), "r"(a[2]), "r"(a[3]),
          "r"(b[0]), "r"(b[1]));
}

__device__ __forceinline__ float gelu_exact(float v) {
    return 0.5f * v * (1.0f + erff(v * 0.70710678118654752440f));
}

__device__ __forceinline__ uint2 f4_to_bf4(float4 v) {
    __nv_bfloat162 p0 = __floats2bfloat162_rn(v.x, v.y);
    __nv_bfloat162 p1 = __floats2bfloat162_rn(v.z, v.w);
    uint2 r;
    r.x = *(uint32_t*)&p0;
    r.y = *(uint32_t*)&p1;
    return r;
}

// ================= router kernel (exact fp32; unchanged) =================
#define RT_CHUNK 1024
#define RT_TPW   2
#define RT_TPB   16

__global__ __launch_bounds__(256)
void router_kernel(const float* __restrict__ r_all,
                   const float* __restrict__ Wr,
                   float* __restrict__ logits_out) {
    __shared__ float wr_s[E_][RT_CHUNK];

    const int tid  = threadIdx.x;
    const int lane = tid & 31;
    const int wid  = tid >> 5;
    const int tok0 = blockIdx.x * RT_TPB + wid * RT_TPW;

    float acc[RT_TPW][E_];
    #pragma unroll
    for (int t = 0; t < RT_TPW; t++)
        #pragma unroll
        for (int e = 0; e < E_; e++) acc[t][e] = 0.f;

    for (int c = 0; c < H_ / RT_CHUNK; c++) {
        __syncthreads();
        #pragma unroll
        for (int i = tid; i < E_ * RT_CHUNK / 4; i += 256) {
            int e  = i >> 8;
            int k4 = i & 255;
            float4 v = *(const float4*)(Wr + (size_t)e * H_ + c * RT_CHUNK + k4 * 4);
            *(float4*)&wr_s[e][k4 * 4] = v;
        }
        __syncthreads();
        #pragma unroll
        for (int t = 0; t < RT_TPW; t++) {
            const float4* rv = (const float4*)(r_all + (size_t)(tok0 + t) * H_ + c * RT_CHUNK);
            for (int k4 = lane; k4 < RT_CHUNK / 4; k4 += 32) {
                float4 r4 = rv[k4];
                #pragma unroll
                for (int e = 0; e < E_; e++) {
                    float4 w4 = *(const float4*)&wr_s[e][k4 * 4];
                    acc[t][e] += r4.x * w4.x + r4.y * w4.y + r4.z * w4.z + r4.w * w4.w;
                }
            }
        }
    }
    #pragma unroll
    for (int t = 0; t < RT_TPW; t++)
        #pragma unroll
        for (int e = 0; e < E_; e++)
            #pragma unroll
            for (int s = 16; s; s >>= 1)
                acc[t][e] += __shfl_xor_sync(0xffffffffu, acc[t][e], s);

    if (lane == 0) {
        #pragma unroll
        for (int t = 0; t < RT_TPW; t++) {
            const int n = tok0 + t;
            float v1 = -INFINITY; int i1 = 0;
            #pragma unroll
            for (int e = 0; e < E_; e++) {
                logits_out[(size_t)n * E_ + e] = acc[t][e];
                if (acc[t][e] > v1) { v1 = acc[t][e]; i1 = e; }
            }
            float v2 = -INFINITY; int i2 = 0;
            #pragma unroll
            for (int e = 0; e < E_; e++) {
                if (e == i1) continue;
                if (acc[t][e] > v2) { v2 = acc[t][e]; i2 = e; }
            }
            float e2 = expf(v2 - v1);
            float w1 = 1.0f / (1.0f + e2);
            float w2 = e2 * w1;
            #pragma unroll
            for (int e = 0; e < E_; e++)
                g_coef[(size_t)n * E_ + e] = (e == i1) ? SCALE * w1 : ((e == i2) ? SCALE * w2 : 0.0f);
        }
    }
}

// ================= GEMM tiling =================
// CTA 128x128, BK=32 (2 k-steps of 16), 256 threads = 8 warps as 4(M) x 2(N),
// warp tile 32x64 = 2 M-frags x 8 N-frags of m16n8k16 bf16.
// Double-buffered smem, register prefetch, one __syncthreads per chunk.
#define BM  128
#define BN  128
#define BK  32
#define BKP 40   // padded bf16 row length: bank stride 20 -> conflict-free frags

// fragment loads from smem buffer
#define LOAD_FRAGS(AsBuf, BsBuf, ks)                                             \
    uint32_t afr[2][4], bfr[8][2];                                               \
    {                                                                            \
        _Pragma("unroll")                                                        \
        for (int mi = 0; mi < 2; mi++) {                                         \
            int r0 = wm + mi * 16 + g;                                           \
            afr[mi][0] = *(const uint32_t*)&AsBuf[r0    ][(ks) * 16 + 2 * tg    ];\
            afr[mi][1] = *(const uint32_t*)&AsBuf[r0 + 8][(ks) * 16 + 2 * tg    ];\
            afr[mi][2] = *(const uint32_t*)&AsBuf[r0    ][(ks) * 16 + 2 * tg + 8];\
            afr[mi][3] = *(const uint32_t*)&AsBuf[r0 + 8][(ks) * 16 + 2 * tg + 8];\
        }                                                                        \
        _Pragma("unroll")                                                        \
        for (int ni = 0; ni < 8; ni++) {                                         \
            int nr = wn + ni * 8 + g;                                            \
            bfr[ni][0] = *(const uint32_t*)&BsBuf[nr][(ks) * 16 + 2 * tg    ];   \
            bfr[ni][1] = *(const uint32_t*)&BsBuf[nr][(ks) * 16 + 2 * tg + 8];   \
        }                                                                        \
    }

#define DO_MMAS()                                                                \
    _Pragma("unroll")                                                            \
    for (int mi = 0; mi < 2; mi++)                                               \
        _Pragma("unroll")                                                        \
        for (int ni = 0; ni < 8; ni++)                                           \
            mma_bf16(c[mi][ni], afr[mi], bfr[ni]);

// ================= down kernel: G = coef * gelu(X @ Wd^T) =================
// X: [NTOK, H] fp32 row-major.  Wd flat: [EA, H] fp32 row-major.
__global__ __launch_bounds__(256)
void down_kernel(const float* __restrict__ X,
                 const float* __restrict__ Wd) {
    __shared__ __nv_bfloat16 As[2][BM][BKP];
    __shared__ __nv_bfloat16 Bs[2][BN][BKP];
    __shared__ float coef_s[BM][E_];

    const int tid  = threadIdx.x;
    const int lane = tid & 31;
    const int wid  = tid >> 5;
    const int g    = lane >> 2;
    const int tg   = lane & 3;
    const int wm   = (wid >> 1) * 32;
    const int wn   = (wid & 1) * 64;
    const int m0   = blockIdx.x * BM;
    const int n0   = blockIdx.y * BN;

    for (int i = tid; i < BM * E_; i += 256)
        coef_s[i / E_][i % E_] = g_coef[(size_t)m0 * E_ + i];

    float c[2][8][4];
    #pragma unroll
    for (int mi = 0; mi < 2; mi++)
        #pragma unroll
        for (int ni = 0; ni < 8; ni++)
            #pragma unroll
            for (int k = 0; k < 4; k++) c[mi][ni][k] = 0.f;

    const int lr = tid >> 3;            // 0..31
    const int lc = (tid & 7) * 4;       // 0..28

    const int NK = H_ / BK;             // 128
    float4 av[4], bv[4];

    // prologue: chunk 0 -> buf 0
    #pragma unroll
    for (int i = 0; i < 4; i++) {
        av[i] = *(const float4*)(X  + (size_t)(m0 + lr + 32 * i) * H_ + lc);
        bv[i] = *(const float4*)(Wd + (size_t)(n0 + lr + 32 * i) * H_ + lc);
    }
    #pragma unroll
    for (int i = 0; i < 4; i++) {
        *(uint2*)&As[0][lr + 32 * i][lc] = f4_to_bf4(av[i]);
        *(uint2*)&Bs[0][lr + 32 * i][lc] = f4_to_bf4(bv[i]);
    }
    __syncthreads();

    for (int kt = 0; kt < NK; kt++) {
        const int b = kt & 1;
        if (kt + 1 < NK) {
            #pragma unroll
            for (int i = 0; i < 4; i++) {
                av[i] = *(const float4*)(X  + (size_t)(m0 + lr + 32 * i) * H_ + (kt + 1) * BK + lc);
                bv[i] = *(const float4*)(Wd + (size_t)(n0 + lr + 32 * i) * H_ + (kt + 1) * BK + lc);
            }
        }
        #pragma unroll
        for (int ks = 0; ks < 2; ks++) {
            LOAD_FRAGS(As[b], Bs[b], ks)
            DO_MMAS()
        }
        if (kt + 1 < NK) {
            #pragma unroll
            for (int i = 0; i < 4; i++) {
                *(uint2*)&As[b ^ 1][lr + 32 * i][lc] = f4_to_bf4(av[i]);
                *(uint2*)&Bs[b ^ 1][lr + 32 * i][lc] = f4_to_bf4(bv[i]);
            }
        }
        __syncthreads();
    }

    // epilogue: gelu + coef -> g_G (bf16)
    #pragma unroll
    for (int mi = 0; mi < 2; mi++) {
        #pragma unroll
        for (int ni = 0; ni < 8; ni++) {
            int r0 = wm + mi * 16 + g;
            int c0 = wn + ni * 8 + 2 * tg;
            int e  = (n0 + c0) >> 6;
            #pragma unroll
            for (int h = 0; h < 2; h++) {          // h=0: row r0, c[0..1]; h=1: row r0+8, c[2..3]
                int rr = r0 + h * 8;
                float cf = coef_s[rr][e];
                float v0 = gelu_exact(c[mi][ni][2 * h + 0]) * cf;
                float v1 = gelu_exact(c[mi][ni][2 * h + 1]) * cf;
                __nv_bfloat162 p = __floats2bfloat162_rn(v0, v1);
                *(uint32_t*)&g_G[(size_t)(m0 + rr) * EA + n0 + c0] = *(uint32_t*)&p;
            }
        }
    }
}

// ================= up kernel: out = o + G @ B,  B[k=ea][n=h] = Wu[e][h][a] =================
__global__ __launch_bounds__(256)
void up_kernel(const float* __restrict__ Wu,
               const float* __restrict__ o_all,
               float* __restrict__ out) {
    __shared__ __nv_bfloat16 As[2][BM][BKP];
    __shared__ __nv_bfloat16 Bs[2][BN][BKP];

    const int tid  = threadIdx.x;
    const int lane = tid & 31;
    const int wid  = tid >> 5;
    const int g    = lane >> 2;
    const int tg   = lane & 3;
    const int wm   = (wid >> 1) * 32;
    const int wn   = (wid & 1) * 64;
    const int m0   = blockIdx.x * BM;   // token tile
    const int n0   = blockIdx.y * BN;   // hidden tile

    float c[2][8][4];
    #pragma unroll
    for (int mi = 0; mi < 2; mi++)
        #pragma unroll
        for (int ni = 0; ni < 8; ni++)
            #pragma unroll
            for (int k = 0; k < 4; k++) c[mi][ni][k] = 0.f;

    const int lr = tid >> 3;
    const int lc = (tid & 7) * 4;

    const int NK = EA / BK;             // 16; chunk kt: expert e = kt>>1, abase = (kt&1)*32
    uint2  avu[4];
    float4 bv[4];

    // prologue: chunk 0 -> buf 0 (e=0, abase=0)
    #pragma unroll
    for (int i = 0; i < 4; i++) {
        avu[i] = *(const uint2*)(g_G + (size_t)(m0 + lr + 32 * i) * EA + lc);
        bv[i]  = *(const float4*)(Wu + (size_t)(n0 + lr + 32 * i) * A_ + lc);
    }
    #pragma unroll
    for (int i = 0; i < 4; i++) {
        *(uint2*)&As[0][lr + 32 * i][lc] = avu[i];
        *(uint2*)&Bs[0][lr + 32 * i][lc] = f4_to_bf4(bv[i]);
    }
    __syncthreads();

    for (int kt = 0; kt < NK; kt++) {
        const int b = kt & 1;
        if (kt + 1 < NK) {
            const int ktn   = kt + 1;
            const int e     = ktn >> 1;
            const int abase = (ktn & 1) * 32;
            #pragma unroll
            for (int i = 0; i < 4; i++) {
                avu[i] = *(const uint2*)(g_G + (size_t)(m0 + lr + 32 * i) * EA + ktn * BK + lc);
                bv[i]  = *(const float4*)(Wu + ((size_t)e * H_ + n0 + lr + 32 * i) * A_ + abase + lc);
            }
        }
        #pragma unroll
        for (int ks = 0; ks < 2; ks++) {
            LOAD_FRAGS(As[b], Bs[b], ks)
            DO_MMAS()
        }
        if (kt + 1 < NK) {
            #pragma unroll
            for (int i = 0; i < 4; i++) {
                *(uint2*)&As[b ^ 1][lr + 32 * i][lc] = avu[i];
                *(uint2*)&Bs[b ^ 1][lr + 32 * i][lc] = f4_to_bf4(bv[i]);
            }
        }
        __syncthreads();
    }

    // epilogue: out = o + D (float2 stores at even columns)
    #pragma unroll
    for (int mi = 0; mi < 2; mi++) {
        #pragma unroll
        for (int ni = 0; ni < 8; ni++) {
            int r0 = wm + mi * 16 + g;
            int c0 = wn + ni * 8 + 2 * tg;
            #pragma unroll
            for (int h = 0; h < 2; h++) {
                int rr = r0 + h * 8;
                size_t idx = (size_t)(m0 + rr) * H_ + n0 + c0;
                float2 ov = *(const float2*)(o_all + idx);
                float2 w;
                w.x = ov.x + c[mi][ni][2 * h + 0];
                w.y = ov.y + c[mi][ni][2 * h + 1];
                *(float2*)(out + idx) = w;
            }
        }
    }
}

// ================= launch =================
extern "C" void kernel_launch(void* const* d_in, const int* in_sizes, int n_in,
                              void* d_out, int out_size) {
    const float* x  = (const float*)d_in[0];
    const float* o  = (const float*)d_in[1];
    const float* r  = (const float*)d_in[2];
    const float* Wr = (const float*)d_in[3];
    const float* Wd = (const float*)d_in[4];
    const float* Wu = (const float*)d_in[5];

    float* out    = (float*)d_out;                 // [NTOK, H]
    float* logits = out + (size_t)NTOK * H_;       // [NTOK, E]

    router_kernel<<<NTOK / RT_TPB, 256>>>(r, Wr, logits);
    down_kernel<<<dim3(NTOK / BM, EA / BN), 256>>>(x, Wd);
    up_kernel<<<dim3(NTOK / BM, H_ / BN), 256>>>(Wu, o, out);
}

// round 5
// speedup vs baseline: 21.8128x; 1.0743x over previous
#include <cuda_runtime.h>
#include <cuda_bf16.h>
#include <math.h>
#include <stdint.h>

// ---------------- problem constants ----------------
#define B_    4
#define S_    2048
#define H_    4096
#define E_    8
#define A_    64
#define NTOK  (B_ * S_)       // 8192
#define EA    (E_ * A_)       // 512
#define SCALE 2.0f

// ---------------- static device scratch ----------------
__device__ float g_coef[NTOK * E_];                          // SCALE * combine weight (0 if unselected)
__device__ __nv_bfloat16 g_G[(size_t)NTOK * EA];             // coef * gelu(X @ Wd^T), bf16
__device__ __nv_bfloat16 g_Xb[(size_t)NTOK * H_];            // X in bf16 (64 MB)
__device__ __nv_bfloat16 g_Wdb[(size_t)EA * H_];             // Wd in bf16
__device__ __nv_bfloat16 g_Wub[(size_t)E_ * H_ * A_];        // Wu in bf16

// ---------------- helpers ----------------
__device__ __forceinline__ void mma_bf16(float* c, const uint32_t* a, const uint32_t* b) {
    asm volatile(
        "mma.sync.aligned.m16n8k16.row.col.f32.bf16.bf16.f32 "
        "{%0,%1,%2,%3}, {%4,%5,%6,%7}, {%8,%9}, {%0,%1,%2,%3};"
        : "+f"(c[0]), "+f"(c[1]), "+f"(c[2]), "+f"(c[3])
        : "r"(a[0]), "r"(a[1]), "r"(a[2]), "r"(a[3]),
          "r"(b[0]), "r"(b[1]));
}

__device__ __forceinline__ void ldsm4(uint32_t& r0, uint32_t& r1, uint32_t& r2, uint32_t& r3,
                                      uint32_t addr) {
    asm volatile("ldmatrix.sync.aligned.m8n8.x4.shared.b16 {%0,%1,%2,%3}, [%4];"
                 : "=r"(r0), "=r"(r1), "=r"(r2), "=r"(r3) : "r"(addr));
}

__device__ __forceinline__ void cp16(uint32_t dst, const void* src) {
    asm volatile("cp.async.cg.shared.global [%0], [%1], 16;" :: "r"(dst), "l"(src));
}
#define CP_COMMIT()  asm volatile("cp.async.commit_group;")
#define CP_WAIT1()   asm volatile("cp.async.wait_group 1;")

__device__ __forceinline__ uint32_t smem_u32(const void* p) {
    uint32_t a;
    asm("{ .reg .u64 t; cvta.to.shared.u64 t, %1; cvt.u32.u64 %0, t; }" : "=r"(a) : "l"(p));
    return a;
}

__device__ __forceinline__ float gelu_exact(float v) {
    return 0.5f * v * (1.0f + erff(v * 0.70710678118654752440f));
}

__device__ __forceinline__ uint2 f4_to_bf4(float4 v) {
    __nv_bfloat162 p0 = __floats2bfloat162_rn(v.x, v.y);
    __nv_bfloat162 p1 = __floats2bfloat162_rn(v.z, v.w);
    uint2 r;
    r.x = *(uint32_t*)&p0;
    r.y = *(uint32_t*)&p1;
    return r;
}

// ================= fp32 -> bf16 convert kernel =================
__global__ __launch_bounds__(256)
void f2bf_kernel(const float* __restrict__ src, __nv_bfloat16* __restrict__ dst) {
    size_t i = ((size_t)blockIdx.x * 256 + threadIdx.x) * 8;
    float4 v0 = *(const float4*)(src + i);
    float4 v1 = *(const float4*)(src + i + 4);
    uint2 a = f4_to_bf4(v0), b = f4_to_bf4(v1);
    uint4 w;
    w.x = a.x; w.y = a.y; w.z = b.x; w.w = b.y;
    *(uint4*)(dst + i) = w;
}

// ================= router kernel (exact fp32) =================
#define RT_CHUNK 1024
#define RT_TPW   2
#define RT_TPB   16

__global__ __launch_bounds__(256)
void router_kernel(const float* __restrict__ r_all,
                   const float* __restrict__ Wr,
                   float* __restrict__ logits_out) {
    __shared__ float wr_s[E_][RT_CHUNK];

    const int tid  = threadIdx.x;
    const int lane = tid & 31;
    const int wid  = tid >> 5;
    const int tok0 = blockIdx.x * RT_TPB + wid * RT_TPW;

    float acc[RT_TPW][E_];
    #pragma unroll
    for (int t = 0; t < RT_TPW; t++)
        #pragma unroll
        for (int e = 0; e < E_; e++) acc[t][e] = 0.f;

    for (int c = 0; c < H_ / RT_CHUNK; c++) {
        __syncthreads();
        #pragma unroll
        for (int i = tid; i < E_ * RT_CHUNK / 4; i += 256) {
            int e  = i >> 8;
            int k4 = i & 255;
            float4 v = *(const float4*)(Wr + (size_t)e * H_ + c * RT_CHUNK + k4 * 4);
            *(float4*)&wr_s[e][k4 * 4] = v;
        }
        __syncthreads();
        #pragma unroll
        for (int t = 0; t < RT_TPW; t++) {
            const float4* rv = (const float4*)(r_all + (size_t)(tok0 + t) * H_ + c * RT_CHUNK);
            for (int k4 = lane; k4 < RT_CHUNK / 4; k4 += 32) {
                float4 r4 = rv[k4];
                #pragma unroll
                for (int e = 0; e < E_; e++) {
                    float4 w4 = *(const float4*)&wr_s[e][k4 * 4];
                    acc[t][e] += r4.x * w4.x + r4.y * w4.y + r4.z * w4.z + r4.w * w4.w;
                }
            }
        }
    }
    #pragma unroll
    for (int t = 0; t < RT_TPW; t++)
        #pragma unroll
        for (int e = 0; e < E_; e++)
            #pragma unroll
            for (int s = 16; s; s >>= 1)
                acc[t][e] += __shfl_xor_sync(0xffffffffu, acc[t][e], s);

    if (lane == 0) {
        #pragma unroll
        for (int t = 0; t < RT_TPW; t++) {
            const int n = tok0 + t;
            float v1 = -INFINITY; int i1 = 0;
            #pragma unroll
            for (int e = 0; e < E_; e++) {
                logits_out[(size_t)n * E_ + e] = acc[t][e];
                if (acc[t][e] > v1) { v1 = acc[t][e]; i1 = e; }
            }
            float v2 = -INFINITY; int i2 = 0;
            #pragma unroll
            for (int e = 0; e < E_; e++) {
                if (e == i1) continue;
                if (acc[t][e] > v2) { v2 = acc[t][e]; i2 = e; }
            }
            float e2 = expf(v2 - v1);
            float w1 = 1.0f / (1.0f + e2);
            float w2 = e2 * w1;
            #pragma unroll
            for (int e = 0; e < E_; e++)
                g_coef[(size_t)n * E_ + e] = (e == i1) ? SCALE * w1 : ((e == i2) ? SCALE * w2 : 0.0f);
        }
    }
}

// ================= GEMM tiling =================
// CTA 128x128, BK=32 bf16 (2 k-steps of 16). 256 threads = 8 warps as 4(M)x2(N),
// warp tile 32x64. 3-stage cp.async pipeline. smem rows: 32 bf16 data + 8 pad = 80 B.
#define BM   128
#define BN   128
#define BK   32
#define ROWB 80
#define TILEB (BM * ROWB)          // 10240 B per tile
#define STAGEB (2 * TILEB)         // A + B per stage
#define SM_COEF 4096
#define SM_NEED (SM_COEF + 3 * STAGEB)   // 65536

// stage one BK chunk of A and B into smem (cp.async, 4x16B per thread)
__device__ __forceinline__ void stage_tiles(uint32_t sA, uint32_t sB,
                                            const __nv_bfloat16* Asrc, size_t lda,
                                            const __nv_bfloat16* Bsrc, size_t ldb,
                                            int tid) {
    const int row = tid >> 1;
    const int co  = (tid & 1) * 16;           // element offset within 32-elem row
    const uint32_t d = (uint32_t)(row * ROWB + co * 2);
    cp16(sA + d,      Asrc + (size_t)row * lda + co);
    cp16(sA + d + 16, Asrc + (size_t)row * lda + co + 8);
    cp16(sB + d,      Bsrc + (size_t)row * ldb + co);
    cp16(sB + d + 16, Bsrc + (size_t)row * ldb + co + 8);
}

// 2 k-steps of ldmatrix + 16 MMAs each
__device__ __forceinline__ void compute_chunk(uint32_t sA, uint32_t sB,
                                              float c[2][8][4],
                                              int wm, int wn, int lane) {
    #pragma unroll
    for (int ks = 0; ks < 2; ks++) {
        uint32_t afr[2][4], bfr[8][2];
        #pragma unroll
        for (int mi = 0; mi < 2; mi++) {
            uint32_t addr = sA + (uint32_t)((wm + mi * 16 + (lane & 15)) * ROWB
                                            + ks * 32 + (lane >> 4) * 16);
            ldsm4(afr[mi][0], afr[mi][1], afr[mi][2], afr[mi][3], addr);
        }
        const int grp = lane >> 3, nis = (grp >> 1), kh = (grp & 1);
        #pragma unroll
        for (int p = 0; p < 4; p++) {
            uint32_t addr = sB + (uint32_t)((wn + (2 * p + nis) * 8 + (lane & 7)) * ROWB
                                            + ks * 32 + kh * 16);
            ldsm4(bfr[2 * p][0], bfr[2 * p][1], bfr[2 * p + 1][0], bfr[2 * p + 1][1], addr);
        }
        #pragma unroll
        for (int mi = 0; mi < 2; mi++)
            #pragma unroll
            for (int ni = 0; ni < 8; ni++)
                mma_bf16(c[mi][ni], afr[mi], bfr[ni]);
    }
}

// ================= down kernel: G = coef * gelu(X @ Wd^T) =================
__global__ __launch_bounds__(256, 2)
void down_kernel() {
    extern __shared__ __align__(16) char sm[];
    float* coef_s = (float*)sm;                 // [BM][E_]
    const uint32_t sb = smem_u32(sm) + SM_COEF;

    const int tid  = threadIdx.x;
    const int lane = tid & 31;
    const int wid  = tid >> 5;
    const int wm   = (wid >> 1) * 32;
    const int wn   = (wid & 1) * 64;
    const int m0   = blockIdx.x * BM;
    const int n0   = blockIdx.y * BN;

    for (int i = tid; i < BM * E_; i += 256)
        coef_s[i] = g_coef[(size_t)m0 * E_ + i];

    float c[2][8][4];
    #pragma unroll
    for (int mi = 0; mi < 2; mi++)
        #pragma unroll
        for (int ni = 0; ni < 8; ni++)
            #pragma unroll
            for (int k = 0; k < 4; k++) c[mi][ni][k] = 0.f;

    const __nv_bfloat16* Ag = g_Xb  + (size_t)m0 * H_;
    const __nv_bfloat16* Bg = g_Wdb + (size_t)n0 * H_;
    const int NK = H_ / BK;                     // 128

    stage_tiles(sb, sb + TILEB, Ag, H_, Bg, H_, tid);
    CP_COMMIT();
    stage_tiles(sb + STAGEB, sb + STAGEB + TILEB, Ag + BK, H_, Bg + BK, H_, tid);
    CP_COMMIT();

    for (int kt = 0; kt < NK; kt++) {
        CP_WAIT1();
        __syncthreads();
        if (kt + 2 < NK) {
            const int s = (kt + 2) % 3;
            stage_tiles(sb + s * STAGEB, sb + s * STAGEB + TILEB,
                        Ag + (size_t)(kt + 2) * BK, H_,
                        Bg + (size_t)(kt + 2) * BK, H_, tid);
        }
        CP_COMMIT();
        const int b = kt % 3;
        compute_chunk(sb + b * STAGEB, sb + b * STAGEB + TILEB, c, wm, wn, lane);
    }

    // epilogue: gelu * coef -> g_G (bf16)
    const int g  = lane >> 2;
    const int tg = lane & 3;
    #pragma unroll
    for (int mi = 0; mi < 2; mi++) {
        #pragma unroll
        for (int ni = 0; ni < 8; ni++) {
            int r0 = wm + mi * 16 + g;
            int c0 = wn + ni * 8 + 2 * tg;
            int e  = (n0 + c0) >> 6;
            #pragma unroll
            for (int h = 0; h < 2; h++) {
                int rr = r0 + h * 8;
                float cf = coef_s[rr * E_ + e];
                float v0 = gelu_exact(c[mi][ni][2 * h + 0]) * cf;
                float v1 = gelu_exact(c[mi][ni][2 * h + 1]) * cf;
                __nv_bfloat162 p = __floats2bfloat162_rn(v0, v1);
                *(uint32_t*)&g_G[(size_t)(m0 + rr) * EA + n0 + c0] = *(uint32_t*)&p;
            }
        }
    }
}

// ================= up kernel: out = o + G @ B,  B[k=ea][n=h] = Wu[e][h][a] =================
__global__ __launch_bounds__(256, 2)
void up_kernel(const float* __restrict__ o_all,
               float* __restrict__ out) {
    extern __shared__ __align__(16) char sm[];
    const uint32_t sb = smem_u32(sm) + SM_COEF;

    const int tid  = threadIdx.x;
    const int lane = tid & 31;
    const int wid  = tid >> 5;
    const int wm   = (wid >> 1) * 32;
    const int wn   = (wid & 1) * 64;
    const int m0   = blockIdx.x * BM;     // token tile
    const int n0   = blockIdx.y * BN;     // hidden tile

    float c[2][8][4];
    #pragma unroll
    for (int mi = 0; mi < 2; mi++)
        #pragma unroll
        for (int ni = 0; ni < 8; ni++)
            #pragma unroll
            for (int k = 0; k < 4; k++) c[mi][ni][k] = 0.f;

    const __nv_bfloat16* Ag = g_G + (size_t)m0 * EA;
    const int NK = EA / BK;               // 16; chunk kt: expert e = kt>>1, abase = (kt&1)*32

    // B source for chunk kt: rows = h (stride A_), base = (e*H_ + n0)*A_ + abase
    #define UP_BSRC(kt) (g_Wub + ((size_t)((kt) >> 1) * H_ + n0) * A_ + ((kt) & 1) * 32)

    stage_tiles(sb, sb + TILEB, Ag, EA, UP_BSRC(0), A_, tid);
    CP_COMMIT();
    stage_tiles(sb + STAGEB, sb + STAGEB + TILEB, Ag + BK, EA, UP_BSRC(1), A_, tid);
    CP_COMMIT();

    for (int kt = 0; kt < NK; kt++) {
        CP_WAIT1();
        __syncthreads();
        if (kt + 2 < NK) {
            const int s = (kt + 2) % 3;
            stage_tiles(sb + s * STAGEB, sb + s * STAGEB + TILEB,
                        Ag + (size_t)(kt + 2) * BK, EA,
                        UP_BSRC(kt + 2), A_, tid);
        }
        CP_COMMIT();
        const int b = kt % 3;
        compute_chunk(sb + b * STAGEB, sb + b * STAGEB + TILEB, c, wm, wn, lane);
    }

    // epilogue: out = o + D
    const int g  = lane >> 2;
    const int tg = lane & 3;
    #pragma unroll
    for (int mi = 0; mi < 2; mi++) {
        #pragma unroll
        for (int ni = 0; ni < 8; ni++) {
            int r0 = wm + mi * 16 + g;
            int c0 = wn + ni * 8 + 2 * tg;
            #pragma unroll
            for (int h = 0; h < 2; h++) {
                int rr = r0 + h * 8;
                size_t idx = (size_t)(m0 + rr) * H_ + n0 + c0;
                float2 ov = *(const float2*)(o_all + idx);
                float2 w;
                w.x = ov.x + c[mi][ni][2 * h + 0];
                w.y = ov.y + c[mi][ni][2 * h + 1];
                *(float2*)(out + idx) = w;
            }
        }
    }
}

// ================= launch =================
extern "C" void kernel_launch(void* const* d_in, const int* in_sizes, int n_in,
                              void* d_out, int out_size) {
    const float* x  = (const float*)d_in[0];
    const float* o  = (const float*)d_in[1];
    const float* r  = (const float*)d_in[2];
    const float* Wr = (const float*)d_in[3];
    const float* Wd = (const float*)d_in[4];
    const float* Wu = (const float*)d_in[5];

    float* out    = (float*)d_out;                 // [NTOK, H]
    float* logits = out + (size_t)NTOK * H_;       // [NTOK, E]

    cudaFuncSetAttribute(down_kernel, cudaFuncAttributeMaxDynamicSharedMemorySize, SM_NEED);
    cudaFuncSetAttribute(up_kernel,   cudaFuncAttributeMaxDynamicSharedMemorySize, SM_NEED);

    __nv_bfloat16* xb;  cudaGetSymbolAddress((void**)&xb,  g_Xb);
    __nv_bfloat16* wdb; cudaGetSymbolAddress((void**)&wdb, g_Wdb);
    __nv_bfloat16* wub; cudaGetSymbolAddress((void**)&wub, g_Wub);

    f2bf_kernel<<<(size_t)NTOK * H_ / (256 * 8), 256>>>(x,  xb);
    f2bf_kernel<<<(size_t)EA * H_ / (256 * 8), 256>>>(Wd, wdb);
    f2bf_kernel<<<(size_t)E_ * H_ * A_ / (256 * 8), 256>>>(Wu, wub);

    router_kernel<<<NTOK / RT_TPB, 256>>>(r, Wr, logits);
    down_kernel<<<dim3(NTOK / BM, EA / BN), 256, SM_NEED>>>();
    up_kernel<<<dim3(NTOK / BM, H_ / BN), 256, SM_NEED>>>(o, out);
}